// round 12
// baseline (speedup 1.0000x reference)
#include <cuda_runtime.h>

// MeshUnpool: out[b,f,t] = (1/occ[b,t]) * sum_e features[b,f,e] * group[b,e,t]
// group ~0.1%-dense 0/1 mask. Stream group once (384 MB) with ld.global.cv
// (L1-bypass; R7 win), record sparse hits, warp-exclusive accumulation.
//
// R12 = R7 geometry (TILE_T=16, grid 1500, the best config: 80.4us) +
// software-pipelined Phase A: double-buffered prefetch (v/w ping-pong,
// outer loop unrolled x2 so there are NO inter-buffer register copies).
// R7's loop drained all outstanding loads at every batch boundary
// (issue=25%, DRAM idle 35%); now each warp keeps 5-10 loads in flight
// continuously. launch_bounds(128,8): 32 warps/SM, ~164 KB in flight.

#define BB 4
#define NF 64
#define EE 4000
#define TT 6000

#define TILE_T 16
#define NLANE  (TILE_T / 4)        // 4 float4 lanes
#define NTHREADS 128
#define NSPLIT (NTHREADS / NLANE)  // 32 E-splits
#define EPT    (EE / NSPLIT)       // 125 rows per split
#define UNROLL 5
#define NITER  (EPT / UNROLL)      // 25
#define NTILES (TT / TILE_T)       // 375 -> grid 1500 (16 divides 6000)
#define HITS_MAX 512

// 4 MB scratch for transposed features [B][E][NF].
__device__ __align__(16) float g_featT[BB * EE * NF];

__device__ __forceinline__ float4 ldcv_f4(const float4* p) {
    float4 v;
    asm volatile("ld.global.cv.v4.f32 {%0,%1,%2,%3}, [%4];"
                 : "=f"(v.x), "=f"(v.y), "=f"(v.z), "=f"(v.w)
                 : "l"(p));
    return v;
}

// ---------------------------------------------------------------------------
// Kernel 1: transpose features [B, NF, E] -> featT [B, E, NF]
// ---------------------------------------------------------------------------
__global__ void transpose_feat_kernel(const float* __restrict__ feat) {
    __shared__ float tile[32][33];
    const int b  = blockIdx.z;
    const int e0 = blockIdx.x * 32;
    const int f0 = blockIdx.y * 32;
    const int tx = threadIdx.x;   // 0..31
    const int ty = threadIdx.y;   // 0..7

#pragma unroll
    for (int j = 0; j < 32; j += 8)
        tile[ty + j][tx] = feat[((size_t)(b * NF + f0 + ty + j)) * EE + e0 + tx];
    __syncthreads();
#pragma unroll
    for (int j = 0; j < 32; j += 8)
        g_featT[((size_t)b * EE + (e0 + ty + j)) * NF + f0 + tx] = tile[tx][ty + j];
}

// ---------------------------------------------------------------------------
// Kernel 2: stream + two-phase sparse accumulate
// ---------------------------------------------------------------------------
__device__ __forceinline__ void load_batch(float4 (&v)[UNROLL],
                                           const float* gbase, int eb) {
#pragma unroll
    for (int u = 0; u < UNROLL; u++)
        v[u] = ldcv_f4(reinterpret_cast<const float4*>(
            gbase + (size_t)(eb + u) * TT));
}

__device__ __forceinline__ void proc_batch(const float4 (&v)[UNROLL], int eb,
                                           int tloc, int* hits, int* nhits) {
    unsigned any = 0;
#pragma unroll
    for (int u = 0; u < UNROLL; u++)
        any |= __float_as_uint(v[u].x) | __float_as_uint(v[u].y) |
               __float_as_uint(v[u].z) | __float_as_uint(v[u].w);
    if (any) {  // rare (~2% of thread-batches)
#pragma unroll
        for (int u = 0; u < UNROLL; u++) {
            const float c[4] = {v[u].x, v[u].y, v[u].z, v[u].w};
#pragma unroll
            for (int k = 0; k < 4; k++) {
                if (__float_as_uint(c[k])) {
                    int idx = atomicAdd(nhits, 1);
                    if (idx < HITS_MAX)
                        hits[idx] = ((eb + u) << 8) | (tloc + k);
                }
            }
        }
    }
}

__global__ void __launch_bounds__(NTHREADS, 8)
unpool_kernel(const float* __restrict__ group,
              const float* __restrict__ occ,
              float* __restrict__ out) {
    __shared__ float acc[TILE_T][NF + 1];   // bank(acc[tt][f]) = (tt+f)%32
    __shared__ float inv_occ[TILE_T];
    __shared__ int   hits[HITS_MAX];        // packed (e << 8) | tt
    __shared__ int   nhits;

    const int b    = blockIdx.x / NTILES;
    const int tile = blockIdx.x % NTILES;
    const int t0   = tile * TILE_T;
    const int tid  = threadIdx.x;

    // init
    for (int i = tid; i < TILE_T * (NF + 1); i += NTHREADS)
        (&acc[0][0])[i] = 0.0f;
    if (tid < TILE_T)
        inv_occ[tid] = 1.0f / occ[(size_t)b * TT + t0 + tid];
    if (tid == 0) nhits = 0;
    __syncthreads();

    // ---- Phase A: software-pipelined stream ----
    const int lane4  = tid & (NLANE - 1);
    const int esplit = tid / NLANE;         // 0..31
    const int tloc   = lane4 * 4;

    {
        const float* gbase = group + (size_t)b * EE * TT + t0 + tloc;
        const int e_begin = esplit * EPT;

        float4 v[UNROLL], w[UNROLL];
        load_batch(v, gbase, e_begin);      // prologue: batch 0 in flight

        for (int it = 0; it < NITER; it += 2) {
            const int eb0 = e_begin + it * UNROLL;
            if (it + 1 < NITER) load_batch(w, gbase, eb0 + UNROLL);
            proc_batch(v, eb0, tloc, hits, &nhits);
            if (it + 2 < NITER) load_batch(v, gbase, eb0 + 2 * UNROLL);
            if (it + 1 < NITER) proc_batch(w, eb0 + UNROLL, tloc, hits, &nhits);
        }
    }
    __syncthreads();

    // ---- Phase B: warp w exclusively owns tt in [4w, 4w+4) ----
    {
        const int wid  = tid >> 5;          // 0..3
        const int lane = tid & 31;
        const int n = (nhits < HITS_MAX) ? nhits : HITS_MAX;
        for (int i = 0; i < n; i++) {
            const int h  = hits[i];         // LDS broadcast
            const int tt = h & 0xFF;
            if ((tt >> 2) == wid) {
                const int e = h >> 8;
                const float* col = g_featT + ((size_t)b * EE + e) * NF;
                // group values at hits are exactly 1.0
                acc[tt][lane]      += col[lane];
                acc[tt][lane + 32] += col[lane + 32];
            }
        }
    }
    __syncthreads();

    // ---- writeout: out[b, f, t0+tt] = acc[tt][f] * inv_occ[tt] ----
    for (int i = tid; i < NF * TILE_T; i += NTHREADS) {
        const int f  = i / TILE_T;
        const int tt = i % TILE_T;
        out[((size_t)b * NF + f) * TT + t0 + tt] = acc[tt][f] * inv_occ[tt];
    }
}

extern "C" void kernel_launch(void* const* d_in, const int* in_sizes, int n_in,
                              void* d_out, int out_size) {
    const float* features = (const float*)d_in[0];   // [B, NF, E]
    const float* group    = (const float*)d_in[1];   // [B, E, T]
    const float* occ      = (const float*)d_in[2];   // [B, T]
    float* out = (float*)d_out;                      // [B, NF, T]

    dim3 tgrid(EE / 32, NF / 32, BB);
    dim3 tblk(32, 8);
    transpose_feat_kernel<<<tgrid, tblk>>>(features);

    unpool_kernel<<<BB * NTILES, NTHREADS>>>(group, occ, out);
}

// round 13
// speedup vs baseline: 1.1182x; 1.1182x over previous
#include <cuda_runtime.h>

// MeshUnpool: out[b,f,t] = (1/occ[b,t]) * sum_e features[b,f,e] * group[b,e,t]
// group ~0.1%-dense 0/1 mask. Stream group once (384 MB) with ld.global.cv
// (L1-bypass; R7 win), record sparse hits, warp-exclusive accumulation.
//
// R13 = R7's exact loop body (the only shape reaching 5.17 TB/s) with more
// resident warps: 160-thread blocks (NSPLIT=40, EPT=100), grid 1500,
// launch_bounds(160,10) -> 50 warps/SM (~78% occ vs R7's 60%).
// Under .cv, measured BW tracks warp count (30%:4.75, 60%:5.17); this is
// the un-probed upper region.

#define BB 4
#define NF 64
#define EE 4000
#define TT 6000

#define TILE_T 16
#define NLANE  (TILE_T / 4)        // 4 float4 lanes
#define NTHREADS 160               // 5 warps
#define NSPLIT (NTHREADS / NLANE)  // 40 E-splits
#define EPT    (EE / NSPLIT)       // 100 rows per split
#define UNROLL 5                   // 20 outer iterations
#define NTILES (TT / TILE_T)       // 375 -> grid 1500
#define HITS_MAX 512

// 4 MB scratch for transposed features [B][E][NF].
__device__ __align__(16) float g_featT[BB * EE * NF];

__device__ __forceinline__ float4 ldcv_f4(const float4* p) {
    float4 v;
    asm volatile("ld.global.cv.v4.f32 {%0,%1,%2,%3}, [%4];"
                 : "=f"(v.x), "=f"(v.y), "=f"(v.z), "=f"(v.w)
                 : "l"(p));
    return v;
}

// ---------------------------------------------------------------------------
// Kernel 1: transpose features [B, NF, E] -> featT [B, E, NF]
// ---------------------------------------------------------------------------
__global__ void transpose_feat_kernel(const float* __restrict__ feat) {
    __shared__ float tile[32][33];
    const int b  = blockIdx.z;
    const int e0 = blockIdx.x * 32;
    const int f0 = blockIdx.y * 32;
    const int tx = threadIdx.x;   // 0..31
    const int ty = threadIdx.y;   // 0..7

#pragma unroll
    for (int j = 0; j < 32; j += 8)
        tile[ty + j][tx] = feat[((size_t)(b * NF + f0 + ty + j)) * EE + e0 + tx];
    __syncthreads();
#pragma unroll
    for (int j = 0; j < 32; j += 8)
        g_featT[((size_t)b * EE + (e0 + ty + j)) * NF + f0 + tx] = tile[tx][ty + j];
}

// ---------------------------------------------------------------------------
// Kernel 2: stream + two-phase sparse accumulate
// ---------------------------------------------------------------------------
__global__ void __launch_bounds__(NTHREADS, 10)
unpool_kernel(const float* __restrict__ group,
              const float* __restrict__ occ,
              float* __restrict__ out) {
    __shared__ float acc[TILE_T][NF + 1];   // bank(acc[tt][f]) = (tt+f)%32
    __shared__ float inv_occ[TILE_T];
    __shared__ int   hits[HITS_MAX];        // packed (e << 8) | tt
    __shared__ int   nhits;

    const int b    = blockIdx.x / NTILES;
    const int tile = blockIdx.x % NTILES;
    const int t0   = tile * TILE_T;
    const int tid  = threadIdx.x;

    // init
    for (int i = tid; i < TILE_T * (NF + 1); i += NTHREADS)
        (&acc[0][0])[i] = 0.0f;
    if (tid < TILE_T)
        inv_occ[tid] = 1.0f / occ[(size_t)b * TT + t0 + tid];
    if (tid == 0) nhits = 0;
    __syncthreads();

    // ---- Phase A: stream group, record nonzero coordinates ----
    const int lane4  = tid & (NLANE - 1);   // which float4 of the tile
    const int esplit = tid / NLANE;         // 0..39
    const int tloc   = lane4 * 4;

    {
        const float* gbase = group + (size_t)b * EE * TT + t0 + tloc;
        const int e_begin = esplit * EPT;
        for (int it = 0; it < EPT / UNROLL; it++) {
            const int eb = e_begin + it * UNROLL;
            float4 v[UNROLL];
#pragma unroll
            for (int u = 0; u < UNROLL; u++)
                v[u] = ldcv_f4(reinterpret_cast<const float4*>(
                    gbase + (size_t)(eb + u) * TT));
            unsigned any = 0;
#pragma unroll
            for (int u = 0; u < UNROLL; u++)
                any |= __float_as_uint(v[u].x) | __float_as_uint(v[u].y) |
                       __float_as_uint(v[u].z) | __float_as_uint(v[u].w);
            if (any) {  // rare (~2% of thread-batches)
#pragma unroll
                for (int u = 0; u < UNROLL; u++) {
                    const float c[4] = {v[u].x, v[u].y, v[u].z, v[u].w};
#pragma unroll
                    for (int k = 0; k < 4; k++) {
                        if (__float_as_uint(c[k])) {
                            int idx = atomicAdd(&nhits, 1);
                            if (idx < HITS_MAX)
                                hits[idx] = ((eb + u) << 8) | (tloc + k);
                        }
                    }
                }
            }
        }
    }
    __syncthreads();

    // ---- Phase B: warps 0-3 own tt in [4w, 4w+4); warp 4 idles ----
    {
        const int wid  = tid >> 5;          // 0..4
        const int lane = tid & 31;
        if (wid < 4) {
            const int n = (nhits < HITS_MAX) ? nhits : HITS_MAX;
            for (int i = 0; i < n; i++) {
                const int h  = hits[i];     // LDS broadcast
                const int tt = h & 0xFF;
                if ((tt >> 2) == wid) {
                    const int e = h >> 8;
                    const float* col = g_featT + ((size_t)b * EE + e) * NF;
                    // group values at hits are exactly 1.0
                    acc[tt][lane]      += col[lane];
                    acc[tt][lane + 32] += col[lane + 32];
                }
            }
        }
    }
    __syncthreads();

    // ---- writeout: out[b, f, t0+tt] = acc[tt][f] * inv_occ[tt] ----
    for (int i = tid; i < NF * TILE_T; i += NTHREADS) {
        const int f  = i / TILE_T;
        const int tt = i % TILE_T;
        out[((size_t)b * NF + f) * TT + t0 + tt] = acc[tt][f] * inv_occ[tt];
    }
}

extern "C" void kernel_launch(void* const* d_in, const int* in_sizes, int n_in,
                              void* d_out, int out_size) {
    const float* features = (const float*)d_in[0];   // [B, NF, E]
    const float* group    = (const float*)d_in[1];   // [B, E, T]
    const float* occ      = (const float*)d_in[2];   // [B, T]
    float* out = (float*)d_out;                      // [B, NF, T]

    dim3 tgrid(EE / 32, NF / 32, BB);
    dim3 tblk(32, 8);
    transpose_feat_kernel<<<tgrid, tblk>>>(features);

    unpool_kernel<<<BB * NTILES, NTHREADS>>>(group, occ, out);
}